// round 5
// baseline (speedup 1.0000x reference)
#include <cuda_runtime.h>
#include <cuda_bf16.h>

// ============================================================================
// GAT layer, restructured as a single fused GEMM:
//   out[b,n,:] = sum_h ( c[b,h,n,0]*h[b,0,:] + c[b,h,n,1]*h[b,1,:] ) @ W_h
// with c = softmax(mask(leakyrelu(src_i + tgt_j))) / 4 (head mean folded in).
// Attention scores need only  h . (W_h @ a_h)  -> tiny precomputed P (256x8).
// W is reordered K-interleaved:  Wr[kk*4+h, dd] = W[kk, h*256+dd]  so that a
// K-chunk of 64 covers (16 kk) x (4 heads) and h is read exactly once.
// ============================================================================

#define NROWS   131072      // B * N_NODES
#define NSAMP   65536
#define BM      128         // node rows per CTA (64 samples)
#define BN      128
#define BK      64          // 16 kk x 4 heads
#define KKC     16
#define NTHREADS 256

__device__ float g_P[256 * 8];        // [kk][h*2 + (0=src,1=tgt)]
__device__ float g_Wr[1024 * 256];    // [kk*4+h][dd]

// ---------------------------------------------------------------- prologues
__global__ void compute_P_kernel(const float* __restrict__ W,
                                 const float* __restrict__ a) {
    int t = blockIdx.x * blockDim.x + threadIdx.x;   // 2048 threads
    if (t >= 2048) return;
    int kk = t >> 3, p = t & 7, h = p >> 1, off = (p & 1) * 256;
    float acc = 0.f;
    #pragma unroll 4
    for (int d = 0; d < 256; d++)
        acc += W[kk * 1024 + h * 256 + d] * a[h * 512 + off + d];
    g_P[kk * 8 + p] = acc;
}

__global__ void reorder_W_kernel(const float* __restrict__ W) {
    int u = blockIdx.x * blockDim.x + threadIdx.x;   // 65536 float4s
    int r = u >> 6, c4 = u & 63;                     // r = kk*4+h
    int kk = r >> 2, h = r & 3;
    float4 v = ((const float4*)W)[kk * 256 + h * 64 + c4];
    ((float4*)g_Wr)[r * 64 + c4] = v;
}

// ---------------------------------------------------------------- main fused
#define PACK2(d, lo, hi) \
    asm("mov.b64 %0, {%1, %2};" : "=l"(d) : "f"(lo), "f"(hi))
#define UNPACK2(lo, hi, v) \
    asm("mov.b64 {%0, %1}, %2;" : "=f"(lo), "=f"(hi) : "l"(v))
#define FMA2(acc, a, b) \
    asm("fma.rn.f32x2 %0, %1, %2, %0;" : "+l"(acc) : "l"(a), "l"(b))

// smem layout (floats)
#define HS_OFF   0                      // [128][260]
#define SA_OFF   33280                  // [128][8]   src/tgt scores
#define CF_OFF   34304                  // [64][4][2][2] coefficients
#define AS_OFF   35328                  // [64][132]  k-major A tile
#define BS_OFF   43776                  // [64][128]
#define SMEM_FLOATS 51968               // 207,872 bytes

__global__ void __launch_bounds__(NTHREADS, 1)
gat_fused_kernel(const float* __restrict__ hin,
                 const int*   __restrict__ adj,
                 float*       __restrict__ out) {
    extern __shared__ float smem[];
    float* hs   = smem + HS_OFF;
    float* sall = smem + SA_OFF;
    float* coef = smem + CF_OFF;
    float* As2  = smem + AS_OFF;
    float* Bs   = smem + BS_OFF;

    const int tid   = threadIdx.x;
    const int n0    = blockIdx.x * BN;       // output column base (0 or 128)
    const int row0  = blockIdx.y * BM;       // global node-row base
    const int samp0 = blockIdx.y * (BM / 2); // global sample base

    // ---- stage h tile: 128 rows x 256 cols, pitch 260 ----
    #pragma unroll
    for (int i = 0; i < 32; i++) {
        int u = i * NTHREADS + tid;
        int r = u >> 6, c4 = u & 63;
        float4 v = ((const float4*)hin)[(row0 + r) * 64 + c4];
        *(float4*)&hs[r * 260 + c4 * 4] = v;
    }
    __syncthreads();

    // ---- src/tgt scores: 128 rows x 8 projections ----
    {
        int p = tid & 7;
        int rb = tid >> 3;                    // 0..31
        float a0 = 0.f, a1 = 0.f, a2 = 0.f, a3 = 0.f;
        #pragma unroll 4
        for (int kk = 0; kk < 256; kk++) {
            float pv = g_P[kk * 8 + p];
            a0 += hs[(rb      ) * 260 + kk] * pv;
            a1 += hs[(rb +  32) * 260 + kk] * pv;
            a2 += hs[(rb +  64) * 260 + kk] * pv;
            a3 += hs[(rb +  96) * 260 + kk] * pv;
        }
        sall[(rb      ) * 8 + p] = a0;
        sall[(rb +  32) * 8 + p] = a1;
        sall[(rb +  64) * 8 + p] = a2;
        sall[(rb +  96) * 8 + p] = a3;
    }
    __syncthreads();

    // ---- attention coefficients: one (sample, head) per thread ----
    {
        int s = tid >> 2, hh = tid & 3;
        const int* ab = adj + (samp0 + s) * 4;
        int m00 = ab[0], m01 = ab[1], m10 = ab[2], m11 = ab[3];
        float s0 = sall[(s * 2 + 0) * 8 + hh * 2];
        float s1 = sall[(s * 2 + 1) * 8 + hh * 2];
        float t0 = sall[(s * 2 + 0) * 8 + hh * 2 + 1];
        float t1 = sall[(s * 2 + 1) * 8 + hh * 2 + 1];
        #pragma unroll
        for (int n = 0; n < 2; n++) {
            float src = n ? s1 : s0;
            int   m0  = n ? m10 : m00;      // adj[n][0]
            int   m1  = n ? m11 : m01;      // adj[n][1]
            float v0 = src + t0;  v0 = v0 > 0.f ? v0 : 0.2f * v0;
            float v1 = src + t1;  v1 = v1 > 0.f ? v1 : 0.2f * v1;
            float w0 = (m0 > 0) ? v0 : -1e30f;
            float w1 = (m1 > 0) ? v1 : -1e30f;
            float mx = fmaxf(w0, w1);
            float e0 = (m0 > 0) ? expf(v0 - mx) : 0.f;
            float e1 = (m1 > 0) ? expf(v1 - mx) : 0.f;
            float inv = 0.25f / (e0 + e1);     // head-mean folded in
            coef[s * 16 + hh * 4 + n * 2 + 0] = e0 * inv;
            coef[s * 16 + hh * 4 + n * 2 + 1] = e1 * inv;
        }
    }
    __syncthreads();

    // ---- hoist this thread's A-gen coefficients (row fixed per thread) ----
    const int myrow = tid & 127;
    const int ms = myrow >> 1;
    const int t7 = tid >> 7;          // 0 or 1 -> which half of heads
    float c0[4], c1[4];
    #pragma unroll
    for (int h = 0; h < 4; h++) {
        c0[h] = coef[ms * 16 + h * 4 + (myrow & 1) * 2 + 0];
        c1[h] = coef[ms * 16 + h * 4 + (myrow & 1) * 2 + 1];
    }

    const int ty = tid >> 4, tx = tid & 15;
    unsigned long long acc[8][4];
    #pragma unroll
    for (int i = 0; i < 8; i++)
        #pragma unroll
        for (int j = 0; j < 4; j++) acc[i][j] = 0ull;   // (0.f,0.f)

    const int pr  = tid >> 5;             // B-stage row this thread handles
    const int pc4 = tid & 31;

    // A-tile generator for chunk kc (reads hs + coefs, writes As2)
    auto gen_A = [&](int kc) {
        #pragma unroll
        for (int kq = 0; kq < 4; kq++) {
            float4 h0q = *(float4*)&hs[(ms * 2    ) * 260 + kc * KKC + kq * 4];
            float4 h1q = *(float4*)&hs[(ms * 2 + 1) * 260 + kc * KKC + kq * 4];
            float h0a[4] = {h0q.x, h0q.y, h0q.z, h0q.w};
            float h1a[4] = {h1q.x, h1q.y, h1q.z, h1q.w};
            #pragma unroll
            for (int j = 0; j < 4; j++) {
                int kkl = kq * 4 + j;
                #pragma unroll
                for (int ii = 0; ii < 2; ii++) {
                    int hh = ii * 2 + t7;
                    As2[(kkl * 4 + hh) * 132 + myrow] =
                        c0[hh] * h0a[j] + c1[hh] * h1a[j];
                }
            }
        }
    };

    // ---- stage chunk 0 (B tile + A tile), then enter pipelined main loop ----
    #pragma unroll
    for (int i = 0; i < 8; i++) {
        float4 v = ((const float4*)g_Wr)[(i * 8 + pr) * 64 + (n0 >> 2) + pc4];
        *(float4*)&Bs[(i * 8 + pr) * 128 + pc4 * 4] = v;
    }
    gen_A(0);
    __syncthreads();

    // ---- main K loop: 16 chunks of BK=64, B prefetched in registers ----
    for (int kc = 0; kc < 16; kc++) {
        float4 pf[8];
        if (kc < 15) {
            #pragma unroll
            for (int i = 0; i < 8; i++)
                pf[i] = ((const float4*)g_Wr)
                        [((kc + 1) * 64 + i * 8 + pr) * 64 + (n0 >> 2) + pc4];
        }

        #pragma unroll 4
        for (int k = 0; k < BK; k++) {
            float4 alo = *(float4*)&As2[k * 132 + ty * 8];
            float4 ahi = *(float4*)&As2[k * 132 + ty * 8 + 4];
            float4 blo = *(float4*)&Bs[k * 128 + tx * 8];
            float4 bhi = *(float4*)&Bs[k * 128 + tx * 8 + 4];
            unsigned long long b2[4];
            PACK2(b2[0], blo.x, blo.y);
            PACK2(b2[1], blo.z, blo.w);
            PACK2(b2[2], bhi.x, bhi.y);
            PACK2(b2[3], bhi.z, bhi.w);
            float av[8] = {alo.x, alo.y, alo.z, alo.w,
                           ahi.x, ahi.y, ahi.z, ahi.w};
            #pragma unroll
            for (int i = 0; i < 8; i++) {
                unsigned long long a2;
                PACK2(a2, av[i], av[i]);
                FMA2(acc[i][0], a2, b2[0]);
                FMA2(acc[i][1], a2, b2[1]);
                FMA2(acc[i][2], a2, b2[2]);
                FMA2(acc[i][3], a2, b2[3]);
            }
        }
        __syncthreads();          // all readers of Bs/As2 done

        if (kc < 15) {
            #pragma unroll
            for (int i = 0; i < 8; i++)
                *(float4*)&Bs[(i * 8 + pr) * 128 + pc4 * 4] = pf[i];
            gen_A(kc + 1);
            __syncthreads();      // tiles for kc+1 visible
        }
    }

    // ---- epilogue: direct stores (out is (B,2,256) row-major) ----
    #pragma unroll
    for (int i = 0; i < 8; i++) {
        int grow = row0 + ty * 8 + i;
        float4 v0, v1;
        UNPACK2(v0.x, v0.y, acc[i][0]);
        UNPACK2(v0.z, v0.w, acc[i][1]);
        UNPACK2(v1.x, v1.y, acc[i][2]);
        UNPACK2(v1.z, v1.w, acc[i][3]);
        float* dst = out + grow * 256 + n0 + tx * 8;
        *(float4*)(dst)     = v0;
        *(float4*)(dst + 4) = v1;
    }
}

// ---------------------------------------------------------------- launch
extern "C" void kernel_launch(void* const* d_in, const int* in_sizes, int n_in,
                              void* d_out, int out_size) {
    const float* h   = (const float*)d_in[0];   // (65536, 2, 256) f32
    const int*   adj = (const int*)  d_in[1];   // (65536, 1, 2, 2) i32
    const float* W   = (const float*)d_in[2];   // (256, 1024) f32
    const float* a   = (const float*)d_in[3];   // (4, 512, 1) f32
    float* out = (float*)d_out;                 // (65536, 2, 256) f32

    compute_P_kernel<<<8, 256>>>(W, a);
    reorder_W_kernel<<<256, 256>>>(W);

    cudaFuncSetAttribute(gat_fused_kernel,
                         cudaFuncAttributeMaxDynamicSharedMemorySize,
                         SMEM_FLOATS * 4);
    dim3 grid(2, NROWS / BM);                   // (2, 1024)
    gat_fused_kernel<<<grid, NTHREADS, SMEM_FLOATS * 4>>>(h, adj, out);
}

// round 15
// speedup vs baseline: 1.8125x; 1.8125x over previous
#include <cuda_runtime.h>
#include <cuda_bf16.h>
#include <cstdint>

// ============================================================================
// GAT layer via warp-level bf16 mma.sync (sm_103 baseline target — tcgen05 is
// not available through this toolchain's compute_103 PTX path).
//   out = G @ Wr,  G[m, kk*4+h] = c0[h,m]*h[m0,kk] + c1[h,m]*h[m1,kk]
// fp32 accuracy via 3-term bf16 split: G@W ~= Gh@Wh + Gl@Wh + Gh@Wl.
// Per CTA: 128 rows x 128 cols, K=1024 in 16 chunks of 64, cp.async B staging.
// ============================================================================

#define TPB   256

__device__ float g_P[256 * 8];        // [kk][h*2 + (0=src,1=tgt)]
__device__ uint4 g_Wbh4[32768];       // bf16 [n=256][k=1024]  hi part of Wr^T
__device__ uint4 g_Wbl4[32768];       // bf16 [n=256][k=1024]  lo part

// ---------------------------------------------------------------- helpers
__device__ __forceinline__ uint32_t smem_u32(const void* p) {
    uint32_t a;
    asm("{ .reg .u64 t; cvta.to.shared.u64 t, %1; cvt.u32.u64 %0, t; }"
        : "=r"(a) : "l"(p));
    return a;
}
#define CP16(s, g) \
    asm volatile("cp.async.cg.shared.global [%0], [%1], 16;" \
                 :: "r"(s), "l"(g) : "memory")
#define CP_COMMIT() asm volatile("cp.async.commit_group;" ::: "memory")
#define CP_WAIT0()  asm volatile("cp.async.wait_group 0;" ::: "memory")

#define LDSM_X4(r, a) \
    asm volatile("ldmatrix.sync.aligned.m8n8.x4.shared.b16 {%0,%1,%2,%3}, [%4];" \
        : "=r"((r)[0]), "=r"((r)[1]), "=r"((r)[2]), "=r"((r)[3]) : "r"(a))

#define MMA_BF16(d, a, b0, b1) \
    asm volatile("mma.sync.aligned.m16n8k16.row.col.f32.bf16.bf16.f32 " \
        "{%0,%1,%2,%3}, {%4,%5,%6,%7}, {%8,%9}, {%0,%1,%2,%3};" \
        : "+f"((d)[0]), "+f"((d)[1]), "+f"((d)[2]), "+f"((d)[3]) \
        : "r"((a)[0]), "r"((a)[1]), "r"((a)[2]), "r"((a)[3]), "r"(b0), "r"(b1))

// ---------------------------------------------------------------- prologues
__global__ void compute_P2_kernel(const float* __restrict__ W,
                                  const float* __restrict__ a) {
    __shared__ float sw[1024];
    __shared__ float sa[2048];
    int kk = blockIdx.x, t = threadIdx.x;
    ((float4*)sw)[t] = ((const float4*)(W + kk * 1024))[t];
    ((float4*)sa)[t]        = ((const float4*)a)[t];
    ((float4*)sa)[t + 256]  = ((const float4*)a)[t + 256];
    __syncthreads();
    int p = t >> 5, lane = t & 31, h = p >> 1, off = (p & 1) * 256;
    float acc = 0.f;
    #pragma unroll
    for (int i = 0; i < 8; i++) {
        int d = lane * 8 + i;
        acc += sw[h * 256 + d] * sa[h * 512 + off + d];
    }
    #pragma unroll
    for (int s = 16; s; s >>= 1) acc += __shfl_xor_sync(0xFFFFFFFFu, acc, s);
    if (lane == 0) g_P[kk * 8 + p] = acc;
}

// Wb[n][k'] = W[kk][hh*256+n], k' = kk*4+hh; split hi/lo bf16
__global__ void build_Wb_kernel(const float* __restrict__ W) {
    int t = blockIdx.x * blockDim.x + threadIdx.x;   // 65536
    int n = t >> 8, kk = t & 255;
    __nv_bfloat16* bh = (__nv_bfloat16*)g_Wbh4;
    __nv_bfloat16* bl = (__nv_bfloat16*)g_Wbl4;
    #pragma unroll
    for (int hh = 0; hh < 4; hh++) {
        float w = W[kk * 1024 + hh * 256 + n];
        __nv_bfloat16 hi = __float2bfloat16(w);
        float r = w - __bfloat162float(hi);
        bh[n * 1024 + kk * 4 + hh] = hi;
        bl[n * 1024 + kk * 4 + hh] = __float2bfloat16(r);
    }
}

// ---------------------------------------------------------------- smem map
// A/B tiles: 128 rows x 64 bf16, pitch 72 bf16 = 144 B  (18432 B each)
#define SM_SP    0          // 8192  (P staged, 2048 f32)
#define SM_SALL  8192       // 4096  (scores 128x8)
#define SM_COEF  12288      // 4096  (coef 64x16)
#define SM_H     16384      // 8192  (h chunk 128x16 f32)
#define SM_AH    24576
#define SM_AL    43008
#define SM_B0H   61440
#define SM_B0L   79872
#define SM_B1H   98304
#define SM_B1L   116736
#define SM_TOTAL 135168

__global__ void __launch_bounds__(TPB, 1)
gat_mma_kernel(const float* __restrict__ hin,
               const int*   __restrict__ adj,
               float*       __restrict__ out) {
    extern __shared__ __align__(1024) char smem[];
    const uint32_t sb = smem_u32(smem);
    float* sP   = (float*)(smem + SM_SP);
    float* sall = (float*)(smem + SM_SALL);
    float* coef = (float*)(smem + SM_COEF);
    float* hbuf = (float*)(smem + SM_H);

    const int tid = threadIdx.x, wid = tid >> 5, lid = tid & 31;
    const int n0    = blockIdx.x * 128;      // output column base (0 or 128)
    const int row0  = blockIdx.y * 128;      // global node-row base
    const int samp0 = blockIdx.y * 64;

    const size_t gWbh = (size_t)__cvta_generic_to_global(g_Wbh4);
    const size_t gWbl = (size_t)__cvta_generic_to_global(g_Wbl4);
    const size_t gH   = (size_t)__cvta_generic_to_global(hin);

    // stage P into smem (2048 f32)
    ((float4*)sP)[tid]       = ((const float4*)g_P)[tid];
    ((float4*)sP)[tid + 256] = ((const float4*)g_P)[tid + 256];
    __syncthreads();

    // ---- score pass: 16 slices of 16 cols through hbuf ----
    {
        const int p = tid & 7, rg = tid >> 3;
        const int r = tid >> 1, hf = tid & 1;
        float accs[4] = {0.f, 0.f, 0.f, 0.f};
        for (int ss = 0; ss < 16; ss++) {
            const float4* src =
                (const float4*)(hin + (row0 + r) * 256 + ss * 16 + hf * 8);
            float4 v0 = src[0], v1 = src[1];
            __syncthreads();
            *(float4*)(hbuf + r * 16 + hf * 8)     = v0;
            *(float4*)(hbuf + r * 16 + hf * 8 + 4) = v1;
            __syncthreads();
            #pragma unroll
            for (int i = 0; i < 4; i++) {
                int rr = rg + i * 32;
                #pragma unroll
                for (int kkl = 0; kkl < 16; kkl++)
                    accs[i] += hbuf[rr * 16 + kkl] * sP[(ss * 16 + kkl) * 8 + p];
            }
        }
        __syncthreads();
        #pragma unroll
        for (int i = 0; i < 4; i++) sall[(rg + i * 32) * 8 + p] = accs[i];
    }
    __syncthreads();

    // ---- attention coefficients: one (sample, head) per thread ----
    {
        int s = tid >> 2, hh = tid & 3;
        const int* ab = adj + (samp0 + s) * 4;
        int m00 = ab[0], m01 = ab[1], m10 = ab[2], m11 = ab[3];
        float s0 = sall[(s * 2 + 0) * 8 + hh * 2];
        float s1 = sall[(s * 2 + 1) * 8 + hh * 2];
        float t0 = sall[(s * 2 + 0) * 8 + hh * 2 + 1];
        float t1 = sall[(s * 2 + 1) * 8 + hh * 2 + 1];
        #pragma unroll
        for (int n = 0; n < 2; n++) {
            float src = n ? s1 : s0;
            int   m0  = n ? m10 : m00;
            int   m1  = n ? m11 : m01;
            float v0 = src + t0;  v0 = v0 > 0.f ? v0 : 0.2f * v0;
            float v1 = src + t1;  v1 = v1 > 0.f ? v1 : 0.2f * v1;
            float w0 = (m0 > 0) ? v0 : -1e30f;
            float w1 = (m1 > 0) ? v1 : -1e30f;
            float mx = fmaxf(w0, w1);
            float e0 = (m0 > 0) ? expf(v0 - mx) : 0.f;
            float e1 = (m1 > 0) ? expf(v1 - mx) : 0.f;
            float inv = 0.25f / (e0 + e1);     // head-mean folded in
            coef[s * 16 + hh * 4 + n * 2 + 0] = e0 * inv;
            coef[s * 16 + hh * 4 + n * 2 + 1] = e1 * inv;
        }
    }
    __syncthreads();

    // ---- per-thread A-gen state (row m = tid>>1, k-half t1 = tid&1) ----
    const int m  = tid >> 1, t1 = tid & 1;
    const int ms = m >> 1,  nn = m & 1;
    const int m0r = m & ~1, m1r = m0r + 1;
    float c0[4], c1[4];
    #pragma unroll
    for (int hh = 0; hh < 4; hh++) {
        c0[hh] = coef[ms * 16 + hh * 4 + nn * 2 + 0];
        c1[hh] = coef[ms * 16 + hh * 4 + nn * 2 + 1];
    }

    // ---- cp.async staging: B (hi+lo) + h chunk ----
    auto issue_cp = [&](int kc, int bbuf) {
        uint32_t dH = sb + (bbuf ? SM_B1H : SM_B0H);
        uint32_t dL = sb + (bbuf ? SM_B1L : SM_B0L);
        #pragma unroll
        for (int i = 0; i < 4; i++) {
            int s = i * TPB + tid, nl = s >> 3, j = s & 7;
            size_t src = (size_t)(n0 + nl) * 2048 + (size_t)kc * 128 + j * 16;
            uint32_t dst = (uint32_t)(nl * 144 + j * 16);
            CP16(dH + dst, gWbh + src);
            CP16(dL + dst, gWbl + src);
        }
        #pragma unroll
        for (int i = 0; i < 2; i++) {
            int s = i * TPB + tid, r = s >> 2, j = s & 3;
            size_t src = ((size_t)(row0 + r) * 256 + kc * 16 + j * 4) * 4;
            CP16(sb + SM_H + r * 64 + j * 16, gH + src);
        }
        CP_COMMIT();
    };

    // ---- A generator: chunk data from hbuf -> Ah/Al (bf16 hi/lo) ----
    auto gen_A = [&]() {
        float4 a0 = *(const float4*)(hbuf + m0r * 16 + t1 * 8);
        float4 a1 = *(const float4*)(hbuf + m0r * 16 + t1 * 8 + 4);
        float4 b0 = *(const float4*)(hbuf + m1r * 16 + t1 * 8);
        float4 b1 = *(const float4*)(hbuf + m1r * 16 + t1 * 8 + 4);
        float h0a[8] = {a0.x, a0.y, a0.z, a0.w, a1.x, a1.y, a1.z, a1.w};
        float h1a[8] = {b0.x, b0.y, b0.z, b0.w, b1.x, b1.y, b1.z, b1.w};
        char* pH = smem + SM_AH + m * 144 + t1 * 64;
        char* pL = smem + SM_AL + m * 144 + t1 * 64;
        #pragma unroll
        for (int q = 0; q < 8; q++) {
            float g[4]; __nv_bfloat16 gh[4], gl[4];
            #pragma unroll
            for (int hh = 0; hh < 4; hh++) {
                g[hh] = c0[hh] * h0a[q] + c1[hh] * h1a[q];
                gh[hh] = __float2bfloat16(g[hh]);
                gl[hh] = __float2bfloat16(g[hh] - __bfloat162float(gh[hh]));
            }
            uint2 uh, ul;
            uh.x = ((uint32_t)__bfloat16_as_ushort(gh[1]) << 16) | __bfloat16_as_ushort(gh[0]);
            uh.y = ((uint32_t)__bfloat16_as_ushort(gh[3]) << 16) | __bfloat16_as_ushort(gh[2]);
            ul.x = ((uint32_t)__bfloat16_as_ushort(gl[1]) << 16) | __bfloat16_as_ushort(gl[0]);
            ul.y = ((uint32_t)__bfloat16_as_ushort(gl[3]) << 16) | __bfloat16_as_ushort(gl[2]);
            *(uint2*)(pH + q * 8) = uh;
            *(uint2*)(pL + q * 8) = ul;
        }
    };

    // ---- warp tiling: 4(m) x 2(n), warp tile 32x64 ----
    const int wm = wid >> 1, wn = wid & 1;
    const int lr = lid & 15, lh = lid >> 4;
    // per-thread ldmatrix base offsets (row + 16B-half), k-step added in loop
    uint32_t aoff[2], boff[4];
    #pragma unroll
    for (int tm = 0; tm < 2; tm++)
        aoff[tm] = (uint32_t)((wm * 32 + tm * 16 + lr) * 144 + lh * 16);
    #pragma unroll
    for (int tb = 0; tb < 4; tb++)
        boff[tb] = (uint32_t)((wn * 64 + tb * 16 + lr) * 144 + lh * 16);

    float acc[2][8][4];
    #pragma unroll
    for (int i = 0; i < 2; i++)
        #pragma unroll
        for (int j = 0; j < 8; j++)
            #pragma unroll
            for (int v = 0; v < 4; v++) acc[i][j][v] = 0.f;

    // ---- preload chunk 0 ----
    issue_cp(0, 0);
    CP_WAIT0();
    __syncthreads();
    gen_A();
    __syncthreads();

    // ---- main loop: 16 chunks of K=64 ----
    for (int kc = 0; kc < 16; kc++) {
        const int b = kc & 1;
        if (kc < 15) issue_cp(kc + 1, b ^ 1);

        const uint32_t bH = sb + (b ? SM_B1H : SM_B0H);
        const uint32_t bL = sb + (b ? SM_B1L : SM_B0L);
        #pragma unroll
        for (int ks = 0; ks < 4; ks++) {
            uint32_t ah[2][4], al[2][4];
            #pragma unroll
            for (int tm = 0; tm < 2; tm++) {
                LDSM_X4(ah[tm], sb + SM_AH + aoff[tm] + ks * 32);
                LDSM_X4(al[tm], sb + SM_AL + aoff[tm] + ks * 32);
            }
            #pragma unroll
            for (int tb = 0; tb < 4; tb++) {
                uint32_t bh[4], bl[4];
                LDSM_X4(bh, bH + boff[tb] + ks * 32);
                LDSM_X4(bl, bL + boff[tb] + ks * 32);
                #pragma unroll
                for (int tm = 0; tm < 2; tm++) {
                    MMA_BF16(acc[tm][tb * 2 + 0], ah[tm], bh[0], bh[2]);
                    MMA_BF16(acc[tm][tb * 2 + 1], ah[tm], bh[1], bh[3]);
                    MMA_BF16(acc[tm][tb * 2 + 0], al[tm], bh[0], bh[2]);
                    MMA_BF16(acc[tm][tb * 2 + 1], al[tm], bh[1], bh[3]);
                    MMA_BF16(acc[tm][tb * 2 + 0], ah[tm], bl[0], bl[2]);
                    MMA_BF16(acc[tm][tb * 2 + 1], ah[tm], bl[1], bl[3]);
                }
            }
        }

        if (kc < 15) {
            CP_WAIT0();
            __syncthreads();   // cp.async data visible; all warps done with A
            gen_A();           // build A tiles for chunk kc+1
            __syncthreads();
        }
    }

    // ---- epilogue: direct stores (out is row-major NROWS x 256) ----
    #pragma unroll
    for (int tm = 0; tm < 2; tm++) {
        int grow = row0 + wm * 32 + tm * 16 + (lid >> 2);
        float* base = out + (size_t)grow * 256 + n0 + wn * 64 + (lid & 3) * 2;
        #pragma unroll
        for (int tn = 0; tn < 8; tn++) {
            float2 v0 = make_float2(acc[tm][tn][0], acc[tm][tn][1]);
            float2 v1 = make_float2(acc[tm][tn][2], acc[tm][tn][3]);
            *(float2*)(base + tn * 8)             = v0;
            *(float2*)(base + tn * 8 + 8 * 256)   = v1;   // row +8
        }
    }
}

// ---------------------------------------------------------------- launch
extern "C" void kernel_launch(void* const* d_in, const int* in_sizes, int n_in,
                              void* d_out, int out_size) {
    const float* h   = (const float*)d_in[0];   // (65536, 2, 256) f32
    const int*   adj = (const int*)  d_in[1];   // (65536, 1, 2, 2) i32
    const float* W   = (const float*)d_in[2];   // (256, 1024) f32
    const float* a   = (const float*)d_in[3];   // (4, 512, 1) f32
    float* out = (float*)d_out;                 // (65536, 2, 256) f32

    compute_P2_kernel<<<256, 256>>>(W, a);
    build_Wb_kernel<<<256, 256>>>(W);

    cudaFuncSetAttribute(gat_mma_kernel,
                         cudaFuncAttributeMaxDynamicSharedMemorySize, SM_TOTAL);
    dim3 grid(2, 1024);
    gat_mma_kernel<<<grid, TPB, SM_TOTAL>>>(h, adj, out);
}